// round 1
// baseline (speedup 1.0000x reference)
#include <cuda_runtime.h>
#include <math.h>
#include <stdint.h>

// Problem dims (fixed by reference)
#define BDIM 64
#define TDIM 4096
#define CDIM 64
#define HDIM 64
#define WDIM 64
#define CONDD 16
#define HID 128
#define INDIM 81          // 1 + 64 + 16
#define K0P 96            // padded layer-0 K (81 -> 96, zero pad)
#define NTOK 128          // tokens per block
#define NTHREADS 256
#define S_MAX 1.5f

#define NTOT (BDIM * TDIM)            // 262144
#define ZSIZE ((size_t)NTOT * 2)      // 524288 floats of z, then 64 floats log_det

// ---------------- device scratch (static, no allocation) ----------------
__device__ float g_wT[(size_t)BDIM * HDIM * WDIM * CDIM];   // 64 MB, [b][y][x][c]
__device__ float g_W0t[4 * K0P * HID];                      // [net][k][out], k>=81 zero
__device__ float g_W1t[4 * 3 * HID * HID];                  // [net*3+layer][k][out]

// ---------------- prep: transpose weights, zero log_det ----------------
__global__ void prep_kernel(const float* __restrict__ W0,
                            const float* __restrict__ W1,
                            float* __restrict__ out) {
    int idx = blockIdx.x * blockDim.x + threadIdx.x;
    const int n0 = 4 * K0P * HID;        // 49152
    if (idx < n0) {
        int i = idx / (K0P * HID);
        int r = idx % (K0P * HID);
        int k = r / HID, o = r % HID;
        g_W0t[idx] = (k < INDIM) ? W0[(i * HID + o) * INDIM + k] : 0.0f;
    }
    const int n1 = 4 * 3 * HID * HID;    // 196608
    if (idx < n1) {
        int g = idx / (HID * HID);
        int r = idx % (HID * HID);
        int k = r / HID, o = r % HID;
        g_W1t[idx] = W1[(g * HID + o) * HID + k];
    }
    if (idx < BDIM) out[ZSIZE + idx] = 0.0f;   // zero log_det accumulators
}

// ---------------- transpose w [B,C,H,W] -> g_wT [B,H,W,C] ----------------
__global__ void transpose_w_kernel(const float* __restrict__ w) {
    __shared__ float tile[64][65];
    int by = blockIdx.x;               // b*H + y
    int b = by / HDIM, y = by % HDIM;
    int tid = threadIdx.x;
    for (int i = tid; i < 64 * 64; i += NTHREADS) {
        int c = i >> 6, xq = i & 63;
        tile[c][xq] = w[(((size_t)b * CDIM + c) * HDIM + y) * WDIM + xq];
    }
    __syncthreads();
    for (int i = tid; i < 64 * 64; i += NTHREADS) {
        int xq = i >> 6, c = i & 63;
        g_wT[(((size_t)b * HDIM + y) * WDIM + xq) * CDIM + c] = tile[c][xq];
    }
}

// ---------------- fused GEMM layer: dst[o][tok] = silu(src.T @ W + b) ----
// src: [K][NTOK] in smem, Wt_g: [K][HID] in gmem (rows contiguous), K % 32 == 0
__device__ __forceinline__ void layer_gemm(const float* __restrict__ src,
                                           float* __restrict__ dst,
                                           const float* __restrict__ Wt_g,
                                           const float* __restrict__ bias_g,
                                           float* Wsm, float* bsm,
                                           int Kdim, int tid) {
    const int tx = tid & 15;    // token group
    const int ty = tid >> 4;    // output group
    float acc[8][8];
#pragma unroll
    for (int i = 0; i < 8; i++)
#pragma unroll
        for (int j = 0; j < 8; j++) acc[i][j] = 0.0f;

    for (int k0 = 0; k0 < Kdim; k0 += 32) {
        // stage 32x128 weight chunk (contiguous 16KB)
        const float4* gsrc = (const float4*)(Wt_g + k0 * HID);
        float4* sdst = (float4*)Wsm;
#pragma unroll
        for (int q = 0; q < 4; q++) sdst[tid + q * NTHREADS] = gsrc[tid + q * NTHREADS];
        __syncthreads();
#pragma unroll
        for (int kk = 0; kk < 32; kk++) {
            float4 a0 = *(const float4*)&src[(k0 + kk) * NTOK + tx * 4];
            float4 a1 = *(const float4*)&src[(k0 + kk) * NTOK + 64 + tx * 4];
            float4 b0 = *(const float4*)&Wsm[kk * HID + ty * 4];
            float4 b1 = *(const float4*)&Wsm[kk * HID + 64 + ty * 4];
            float av[8] = {a0.x, a0.y, a0.z, a0.w, a1.x, a1.y, a1.z, a1.w};
            float bv[8] = {b0.x, b0.y, b0.z, b0.w, b1.x, b1.y, b1.z, b1.w};
#pragma unroll
            for (int i = 0; i < 8; i++)
#pragma unroll
                for (int j = 0; j < 8; j++) acc[i][j] += bv[i] * av[j];
        }
        __syncthreads();
    }
    if (tid < HID) bsm[tid] = bias_g[tid];
    __syncthreads();
#pragma unroll
    for (int i = 0; i < 8; i++) {
        int o = (i < 4) ? (ty * 4 + i) : (64 + ty * 4 + i - 4);
        float bb = bsm[o];
        float v[8];
#pragma unroll
        for (int j = 0; j < 8; j++) {
            float z = acc[i][j] + bb;
            v[j] = z / (1.0f + __expf(-z));   // silu
        }
        *(float4*)&dst[o * NTOK + tx * 4]      = make_float4(v[0], v[1], v[2], v[3]);
        *(float4*)&dst[o * NTOK + 64 + tx * 4] = make_float4(v[4], v[5], v[6], v[7]);
    }
    __syncthreads();
}

// final 128 -> 1 dot per token
__device__ __forceinline__ void final_dot(const float* __restrict__ src,
                                          const float* __restrict__ w2_g,
                                          float b2v, float* dstArr,
                                          float* wsm, int tid) {
    if (tid < HID) wsm[tid] = w2_g[tid];
    __syncthreads();
    if (tid < NTOK) {
        float s = 0.0f;
#pragma unroll 8
        for (int k = 0; k < HID; k++) s += src[k * NTOK + tid] * wsm[k];
        dstArr[tid] = s + b2v;
    }
    __syncthreads();
}

// ---------------- phase kernel ----------------
template <int PHASE>
__global__ __launch_bounds__(NTHREADS, 1)
void phase_kernel(const float* __restrict__ x,
                  const float* __restrict__ cond,
                  const float* __restrict__ b0,
                  const float* __restrict__ b1,
                  const float* __restrict__ W2,
                  const float* __restrict__ b2,
                  float* __restrict__ out) {
    extern __shared__ float sm[];
    float* comb = sm;                       // 96*128
    float* hA   = comb + K0P * NTOK;        // 128*128
    float* hB   = hA + HID * NTOK;          // 128*128
    float* Wsm  = hB + HID * NTOK;          // 32*128
    float* bsm  = Wsm + 32 * HID;           // 128
    float* sArr = bsm + HID;                // 128
    float* tArr = sArr + NTOK;              // 128

    const int tid = threadIdx.x;
    const int nbase = blockIdx.x * NTOK;
    const int b = nbase / TDIM;             // constant per block (TDIM % NTOK == 0)

    // ---- build comb[feat][tok]: [z_keep | lf(64) | cond(16) | pad(15)] ----
    {
        int tk = tid >> 1;
        int half = tid & 1;
        int n = nbase + tk;
        float zx, zy, zkeep;
        if (PHASE == 1) { zx = x[2 * n]; zy = x[2 * n + 1]; zkeep = zy; }
        else           { zx = out[2 * n]; zy = x[2 * n + 1]; zkeep = zx; }
        float ix = zx * 63.0f, iy = zy * 63.0f;
        float ix0 = floorf(ix), iy0 = floorf(iy);
        float wx1 = ix - ix0, wx0 = 1.0f - wx1;
        float wy1 = iy - iy0, wy0 = 1.0f - wy1;
        float acc[32];
#pragma unroll
        for (int c = 0; c < 32; c++) acc[c] = 0.0f;
#pragma unroll
        for (int corner = 0; corner < 4; corner++) {
            int dx = corner & 1, dy = corner >> 1;
            float xx = ix0 + (float)dx, yy = iy0 + (float)dy;
            bool valid = (xx >= 0.0f) && (xx <= 63.0f) && (yy >= 0.0f) && (yy <= 63.0f);
            if (valid) {
                float wgt = (dx ? wx1 : wx0) * (dy ? wy1 : wy0);
                int xc = (int)fminf(fmaxf(xx, 0.0f), 63.0f);
                int yc = (int)fminf(fmaxf(yy, 0.0f), 63.0f);
                const float4* gp = (const float4*)(g_wT +
                    ((((size_t)b * HDIM + yc) * WDIM + xc) * CDIM) + half * 32);
#pragma unroll
                for (int q = 0; q < 8; q++) {
                    float4 v = gp[q];
                    acc[q * 4 + 0] += wgt * v.x;
                    acc[q * 4 + 1] += wgt * v.y;
                    acc[q * 4 + 2] += wgt * v.z;
                    acc[q * 4 + 3] += wgt * v.w;
                }
            }
        }
#pragma unroll
        for (int c = 0; c < 32; c++)
            comb[(1 + half * 32 + c) * NTOK + tk] = acc[c];
        if (half == 0) {
            comb[0 * NTOK + tk] = zkeep;
        } else {
#pragma unroll
            for (int r = INDIM; r < K0P; r++) comb[r * NTOK + tk] = 0.0f;
        }
    }
    for (int i = tid; i < CONDD * NTOK; i += NTHREADS) {
        int j = i / NTOK, tk = i % NTOK;
        comb[(1 + CDIM + j) * NTOK + tk] = cond[b * CONDD + j];
    }
    __syncthreads();

    const int idx_s = (PHASE == 1) ? 0 : 2;
    const int idx_t = idx_s + 1;

    // ---- s-net ----
    layer_gemm(comb, hA, g_W0t + idx_s * K0P * HID, b0 + idx_s * HID, Wsm, bsm, K0P, tid);
    layer_gemm(hA, hB, g_W1t + (idx_s * 3 + 0) * HID * HID, b1 + (idx_s * 3 + 0) * HID, Wsm, bsm, HID, tid);
    layer_gemm(hB, hA, g_W1t + (idx_s * 3 + 1) * HID * HID, b1 + (idx_s * 3 + 1) * HID, Wsm, bsm, HID, tid);
    layer_gemm(hA, hB, g_W1t + (idx_s * 3 + 2) * HID * HID, b1 + (idx_s * 3 + 2) * HID, Wsm, bsm, HID, tid);
    final_dot(hB, W2 + idx_s * HID, b2[idx_s], sArr, bsm, tid);

    // ---- t-net ----
    layer_gemm(comb, hA, g_W0t + idx_t * K0P * HID, b0 + idx_t * HID, Wsm, bsm, K0P, tid);
    layer_gemm(hA, hB, g_W1t + (idx_t * 3 + 0) * HID * HID, b1 + (idx_t * 3 + 0) * HID, Wsm, bsm, HID, tid);
    layer_gemm(hB, hA, g_W1t + (idx_t * 3 + 1) * HID * HID, b1 + (idx_t * 3 + 1) * HID, Wsm, bsm, HID, tid);
    layer_gemm(hA, hB, g_W1t + (idx_t * 3 + 2) * HID * HID, b1 + (idx_t * 3 + 2) * HID, Wsm, bsm, HID, tid);
    final_dot(hB, W2 + idx_t * HID, b2[idx_t], tArr, bsm, tid);

    // ---- epilogue ----
    if (tid < NTOK) {
        int n = nbase + tid;
        float s = tanhf(sArr[tid]) * S_MAX;
        float t = tArr[tid];
        float zold = (PHASE == 1) ? x[2 * n] : x[2 * n + 1];
        float znew = zold * expf(s) + t;
        out[2 * n + ((PHASE == 1) ? 0 : 1)] = znew;
        sArr[tid] = s;
    }
    __syncthreads();
    if (tid < 32) {
        float v = sArr[tid] + sArr[tid + 32] + sArr[tid + 64] + sArr[tid + 96];
#pragma unroll
        for (int off = 16; off > 0; off >>= 1) v += __shfl_down_sync(0xffffffffu, v, off);
        if (tid == 0) atomicAdd(out + ZSIZE + b, v);
    }
}

// ---------------- launch ----------------
extern "C" void kernel_launch(void* const* d_in, const int* in_sizes, int n_in,
                              void* d_out, int out_size) {
    const float* x    = (const float*)d_in[0];
    const float* w    = (const float*)d_in[1];
    const float* cond = (const float*)d_in[2];
    const float* W0   = (const float*)d_in[3];
    const float* b0   = (const float*)d_in[4];
    const float* W1   = (const float*)d_in[5];
    const float* b1   = (const float*)d_in[6];
    const float* W2   = (const float*)d_in[7];
    const float* b2   = (const float*)d_in[8];
    float* out = (float*)d_out;

    const size_t smem = (size_t)(K0P * NTOK + 2 * HID * NTOK + 32 * HID +
                                 HID + 2 * NTOK) * sizeof(float);  // ~194 KB
    cudaFuncSetAttribute(phase_kernel<1>, cudaFuncAttributeMaxDynamicSharedMemorySize, (int)smem);
    cudaFuncSetAttribute(phase_kernel<2>, cudaFuncAttributeMaxDynamicSharedMemorySize, (int)smem);

    prep_kernel<<<768, NTHREADS>>>(W0, W1, out);
    transpose_w_kernel<<<BDIM * HDIM, NTHREADS>>>(w);
    phase_kernel<1><<<NTOT / NTOK, NTHREADS, smem>>>(x, cond, b0, b1, W2, b2, out);
    phase_kernel<2><<<NTOT / NTOK, NTHREADS, smem>>>(x, cond, b0, b1, W2, b2, out);
}

// round 2
// speedup vs baseline: 2.9113x; 2.9113x over previous
#include <cuda_runtime.h>
#include <cuda_bf16.h>
#include <math.h>
#include <stdint.h>

// Problem dims (fixed by reference)
#define BDIM 64
#define TDIM 4096
#define CDIM 64
#define HDIM 64
#define WDIM 64
#define CONDD 16
#define HID 128
#define INDIM 81
#define K0P 96            // padded layer-0 K (81 -> 96)
#define NTOK 256          // tokens per block
#define NTHREADS 256
#define PITCH 136         // bf16 row pitch (128 + 8) -> conflict-free LDSM
#define PITCH_U32 68
#define S_MAX 1.5f

#define NTOT (BDIM * TDIM)            // 262144
#define ZSIZE ((size_t)NTOT * 2)      // 524288 floats of z, then 64 floats log_det

// ---------------- device scratch (static, no allocation) ----------------
__device__ float g_wT[(size_t)BDIM * HDIM * WDIM * CDIM];   // 64 MB, [b][y][x][c]
__device__ __align__(16) __nv_bfloat16 g_W0h[4 * K0P * HID];
__device__ __align__(16) __nv_bfloat16 g_W0l[4 * K0P * HID];
__device__ __align__(16) __nv_bfloat16 g_W1h[12 * HID * HID];
__device__ __align__(16) __nv_bfloat16 g_W1l[12 * HID * HID];

// ---------------- helpers ----------------
__device__ __forceinline__ float silu_f(float z) {
    return __fdividef(z, 1.0f + __expf(-z));
}

__device__ __forceinline__ void ldsm_x4(uint32_t d[4], uint32_t saddr) {
    asm volatile("ldmatrix.sync.aligned.m8n8.x4.shared.b16 {%0,%1,%2,%3}, [%4];\n"
        : "=r"(d[0]), "=r"(d[1]), "=r"(d[2]), "=r"(d[3]) : "r"(saddr));
}
__device__ __forceinline__ void ldsm_x4_t(uint32_t d[4], uint32_t saddr) {
    asm volatile("ldmatrix.sync.aligned.m8n8.x4.trans.shared.b16 {%0,%1,%2,%3}, [%4];\n"
        : "=r"(d[0]), "=r"(d[1]), "=r"(d[2]), "=r"(d[3]) : "r"(saddr));
}
__device__ __forceinline__ void mma_bf16(float c[4], const uint32_t a[4],
                                         uint32_t b0, uint32_t b1) {
    asm volatile(
        "mma.sync.aligned.m16n8k16.row.col.f32.bf16.bf16.f32 "
        "{%0,%1,%2,%3}, {%4,%5,%6,%7}, {%8,%9}, {%0,%1,%2,%3};\n"
        : "+f"(c[0]), "+f"(c[1]), "+f"(c[2]), "+f"(c[3])
        : "r"(a[0]), "r"(a[1]), "r"(a[2]), "r"(a[3]), "r"(b0), "r"(b1));
}

__device__ __forceinline__ void split_store_pair(uint32_t* H, uint32_t* L,
                                                 int row, int n0, float a, float b) {
    __nv_bfloat16 ah = __float2bfloat16_rn(a);
    __nv_bfloat16 bh = __float2bfloat16_rn(b);
    float ar = a - __bfloat162float(ah);
    float br = b - __bfloat162float(bh);
    __nv_bfloat162 hp = __halves2bfloat162(ah, bh);
    __nv_bfloat162 lp = __halves2bfloat162(__float2bfloat16_rn(ar), __float2bfloat16_rn(br));
    H[row * PITCH_U32 + (n0 >> 1)] = *reinterpret_cast<uint32_t*>(&hp);
    L[row * PITCH_U32 + (n0 >> 1)] = *reinterpret_cast<uint32_t*>(&lp);
}

// ---------------- prep: split weights to bf16 hi/lo, zero log_det ----------
__global__ void prep_kernel(const float* __restrict__ W0,
                            const float* __restrict__ W1,
                            float* __restrict__ out) {
    int idx = blockIdx.x * blockDim.x + threadIdx.x;
    // layer 0: new k-order [lf(64) | cond(16) | z(1) | pad]; layout [net][k][n]
    if (idx < 4 * K0P * HID) {
        int i = idx / (K0P * HID);
        int r = idx % (K0P * HID);
        int k = r >> 7, nn = r & 127;
        float v = 0.0f;
        if (k <= 80) {
            int korig = (k < 80) ? (k + 1) : 0;
            v = W0[(i * HID + nn) * INDIM + korig];
        }
        __nv_bfloat16 h = __float2bfloat16_rn(v);
        g_W0h[idx] = h;
        g_W0l[idx] = __float2bfloat16_rn(v - __bfloat162float(h));
    }
    // layers 1-3: layout [g][k][n]
    if (idx < 12 * HID * HID) {
        int g = idx >> 14;
        int r = idx & 16383;
        int k = r >> 7, nn = r & 127;
        float v = W1[(g * HID + nn) * HID + k];
        __nv_bfloat16 h = __float2bfloat16_rn(v);
        g_W1h[idx] = h;
        g_W1l[idx] = __float2bfloat16_rn(v - __bfloat162float(h));
    }
    if (idx < BDIM) out[ZSIZE + idx] = 0.0f;
}

// ---------------- transpose w [B,C,H,W] -> g_wT [B,H,W,C] ----------------
__global__ void transpose_w_kernel(const float* __restrict__ w) {
    __shared__ float tile[64][65];
    int by = blockIdx.x;
    int b = by / HDIM, y = by % HDIM;
    int tid = threadIdx.x;
    for (int i = tid; i < 64 * 64; i += NTHREADS) {
        int c = i >> 6, xq = i & 63;
        tile[c][xq] = w[(((size_t)b * CDIM + c) * HDIM + y) * WDIM + xq];
    }
    __syncthreads();
    for (int i = tid; i < 64 * 64; i += NTHREADS) {
        int xq = i >> 6, c = i & 63;
        g_wT[(((size_t)b * HDIM + y) * WDIM + xq) * CDIM + c] = tile[c][xq];
    }
}

// ---------------- phase kernel ----------------
template <int PHASE>
__global__ __launch_bounds__(NTHREADS, 1)
void phase_kernel(const float* __restrict__ x,
                  const float* __restrict__ cond,
                  const float* __restrict__ b0g,
                  const float* __restrict__ b1g,
                  const float* __restrict__ W2g,
                  const float* __restrict__ b2g,
                  float* __restrict__ out) {
    extern __shared__ char smraw[];
    __nv_bfloat16* actH = (__nv_bfloat16*)smraw;
    __nv_bfloat16* actL = actH + NTOK * PITCH;
    __nv_bfloat16* WsmH = actL + NTOK * PITCH;
    __nv_bfloat16* WsmL = WsmH + HID * PITCH;
    float* sArr = (float*)(WsmL + HID * PITCH);
    float* tArr = sArr + NTOK;
    float* w2sm = tArr + NTOK;

    const int tid = threadIdx.x;
    const int lane = tid & 31;
    const int wid = tid >> 5;
    const int tokBase = (wid & 3) * 64;
    const int nBase = (wid >> 2) * 64;
    const int nbase = blockIdx.x * NTOK;
    const int b = nbase >> 12;                 // 4096 tokens per b; 256 | 4096

    uint32_t actH_s = (uint32_t)__cvta_generic_to_shared(actH);
    uint32_t actL_s = (uint32_t)__cvta_generic_to_shared(actL);
    uint32_t WsmH_s = (uint32_t)__cvta_generic_to_shared(WsmH);
    uint32_t WsmL_s = (uint32_t)__cvta_generic_to_shared(WsmL);
    uint32_t* actH_u = (uint32_t*)actH;
    uint32_t* actL_u = (uint32_t*)actL;

    const int r8 = lane & 7;
    const int gA = (lane >> 3) & 1;
    const int gB = lane >> 4;

    for (int half = 0; half < 2; ++half) {
        const int net = ((PHASE == 1) ? 0 : 2) + half;

        // ---- gather: build comb row per token: [lf(64)|cond(16)|z|0...] ----
        {
            int n = nbase + tid;
            float zx, zy, zkeep;
            if (PHASE == 1) { zx = x[2 * n]; zy = x[2 * n + 1]; zkeep = zy; }
            else            { zx = out[2 * n]; zy = x[2 * n + 1]; zkeep = zx; }
            float ix = zx * 63.0f, iy = zy * 63.0f;
            float ix0 = floorf(ix), iy0 = floorf(iy);
            float wx1 = ix - ix0, wx0 = 1.0f - wx1;
            float wy1 = iy - iy0, wy0 = 1.0f - wy1;
            float acc[64];
#pragma unroll
            for (int c = 0; c < 64; c++) acc[c] = 0.0f;
#pragma unroll
            for (int corner = 0; corner < 4; corner++) {
                int dx = corner & 1, dy = corner >> 1;
                float xx = ix0 + (float)dx, yy = iy0 + (float)dy;
                bool valid = (xx >= 0.0f) && (xx <= 63.0f) && (yy >= 0.0f) && (yy <= 63.0f);
                if (valid) {
                    float wgt = (dx ? wx1 : wx0) * (dy ? wy1 : wy0);
                    int xc = (int)xx, yc = (int)yy;
                    const float4* gp = (const float4*)(g_wT +
                        (((size_t)b * HDIM + yc) * WDIM + xc) * CDIM);
#pragma unroll
                    for (int q = 0; q < 16; q++) {
                        float4 v = gp[q];
                        acc[q * 4 + 0] += wgt * v.x;
                        acc[q * 4 + 1] += wgt * v.y;
                        acc[q * 4 + 2] += wgt * v.z;
                        acc[q * 4 + 3] += wgt * v.w;
                    }
                }
            }
#pragma unroll
            for (int c = 0; c < 32; c++)
                split_store_pair(actH_u, actL_u, tid, 2 * c, acc[2 * c], acc[2 * c + 1]);
#pragma unroll
            for (int j = 0; j < 8; j++) {
                float c0 = cond[b * CONDD + 2 * j];
                float c1 = cond[b * CONDD + 2 * j + 1];
                split_store_pair(actH_u, actL_u, tid, 64 + 2 * j, c0, c1);
            }
            split_store_pair(actH_u, actL_u, tid, 80, zkeep, 0.0f);
#pragma unroll
            for (int q = 41; q < 48; q++) {
                actH_u[tid * PITCH_U32 + q] = 0u;
                actL_u[tid * PITCH_U32 + q] = 0u;
            }
        }
        __syncthreads();

        // ---- 4 GEMM+silu layers ----
        for (int l = 0; l < 4; ++l) {
            const __nv_bfloat16* gWh;
            const __nv_bfloat16* gWl;
            const float* bias;
            int K;
            if (l == 0) {
                gWh = g_W0h + net * K0P * HID;
                gWl = g_W0l + net * K0P * HID;
                bias = b0g + net * HID;
                K = K0P;
            } else {
                int g = net * 3 + (l - 1);
                gWh = g_W1h + g * HID * HID;
                gWl = g_W1l + g * HID * HID;
                bias = b1g + g * HID;
                K = HID;
            }
            // stage weights (contiguous gmem -> pitched smem, 16B chunks)
            {
                const float4* sh = (const float4*)gWh;
                const float4* sl = (const float4*)gWl;
                float4* dh = (float4*)WsmH;
                float4* dl = (float4*)WsmL;
                int chunks = K * 16;           // 16 float4 per 128-bf16 row
                for (int i = tid; i < chunks; i += NTHREADS) {
                    int k = i >> 4, c = i & 15;
                    dh[k * 17 + c] = sh[i];
                    dl[k * 17 + c] = sl[i];
                }
            }
            __syncthreads();

            float acc[4][8][4];
#pragma unroll
            for (int mi = 0; mi < 4; mi++)
#pragma unroll
                for (int nj = 0; nj < 8; nj++)
#pragma unroll
                    for (int q = 0; q < 4; q++) acc[mi][nj][q] = 0.0f;

            const int ksteps = K >> 4;
            for (int ks = 0; ks < ksteps; ++ks) {
                uint32_t aH[4][4], aL[4][4];
                int colA = ks * 16 + gB * 8;
#pragma unroll
                for (int mi = 0; mi < 4; mi++) {
                    uint32_t off = (uint32_t)(((tokBase + mi * 16 + r8 + gA * 8) * PITCH + colA) * 2);
                    ldsm_x4(aH[mi], actH_s + off);
                    ldsm_x4(aL[mi], actL_s + off);
                }
#pragma unroll
                for (int nj = 0; nj < 4; nj++) {
                    uint32_t bH[4], bL[4];
                    uint32_t off = (uint32_t)(((ks * 16 + r8 + gA * 8) * PITCH +
                                               nBase + nj * 16 + gB * 8) * 2);
                    ldsm_x4_t(bH, WsmH_s + off);
                    ldsm_x4_t(bL, WsmL_s + off);
#pragma unroll
                    for (int mi = 0; mi < 4; mi++) {
#pragma unroll
                        for (int h2 = 0; h2 < 2; h2++) {
                            float* c4 = acc[mi][nj * 2 + h2];
                            mma_bf16(c4, aH[mi], bH[2 * h2], bH[2 * h2 + 1]);
                            mma_bf16(c4, aH[mi], bL[2 * h2], bL[2 * h2 + 1]);
                            mma_bf16(c4, aL[mi], bH[2 * h2], bH[2 * h2 + 1]);
                        }
                    }
                }
            }
            __syncthreads();   // all reads done before in-place act overwrite

            // epilogue: bias + silu -> split bf16 hi/lo -> act buffer
#pragma unroll
            for (int mi = 0; mi < 4; mi++) {
                int row0 = tokBase + mi * 16 + (lane >> 2);
#pragma unroll
                for (int n8 = 0; n8 < 8; n8++) {
                    int n0 = nBase + n8 * 8 + (lane & 3) * 2;
                    float2 bb = *(const float2*)&bias[n0];
                    float* d = acc[mi][n8];
                    float h00 = silu_f(d[0] + bb.x);
                    float h01 = silu_f(d[1] + bb.y);
                    float h10 = silu_f(d[2] + bb.x);
                    float h11 = silu_f(d[3] + bb.y);
                    split_store_pair(actH_u, actL_u, row0, n0, h00, h01);
                    split_store_pair(actH_u, actL_u, row0 + 8, n0, h10, h11);
                }
            }
            __syncthreads();
        }

        // ---- final 128 -> 1 dot ----
        if (tid < HID) w2sm[tid] = W2g[net * HID + tid];
        __syncthreads();
        {
            float sum = 0.0f;
            int rowOff = tid * PITCH_U32;
#pragma unroll 8
            for (int i = 0; i < 64; ++i) {
                uint32_t hp = actH_u[rowOff + i];
                uint32_t lp = actL_u[rowOff + i];
                __nv_bfloat162 hv = *reinterpret_cast<__nv_bfloat162*>(&hp);
                __nv_bfloat162 lv = *reinterpret_cast<__nv_bfloat162*>(&lp);
                float v0 = __bfloat162float(hv.x) + __bfloat162float(lv.x);
                float v1 = __bfloat162float(hv.y) + __bfloat162float(lv.y);
                sum += v0 * w2sm[2 * i] + v1 * w2sm[2 * i + 1];
            }
            float* dst = (half == 0) ? sArr : tArr;
            dst[tid] = sum + b2g[net];
        }
        __syncthreads();
    }

    // ---- coupling update + log_det ----
    {
        int n = nbase + tid;
        float s = tanhf(sArr[tid]) * S_MAX;
        float t = tArr[tid];
        float zold = (PHASE == 1) ? x[2 * n] : x[2 * n + 1];
        out[2 * n + ((PHASE == 1) ? 0 : 1)] = zold * expf(s) + t;
        sArr[tid] = s;
    }
    __syncthreads();
    if (tid < 32) {
        float v = 0.0f;
#pragma unroll
        for (int j = 0; j < 8; j++) v += sArr[tid + 32 * j];
#pragma unroll
        for (int off = 16; off > 0; off >>= 1) v += __shfl_down_sync(0xffffffffu, v, off);
        if (tid == 0) atomicAdd(out + ZSIZE + b, v);
    }
}

// ---------------- launch ----------------
extern "C" void kernel_launch(void* const* d_in, const int* in_sizes, int n_in,
                              void* d_out, int out_size) {
    const float* x    = (const float*)d_in[0];
    const float* w    = (const float*)d_in[1];
    const float* cond = (const float*)d_in[2];
    const float* W0   = (const float*)d_in[3];
    const float* b0   = (const float*)d_in[4];
    const float* W1   = (const float*)d_in[5];
    const float* b1   = (const float*)d_in[6];
    const float* W2   = (const float*)d_in[7];
    const float* b2   = (const float*)d_in[8];
    float* out = (float*)d_out;

    const size_t smem = (size_t)(NTOK * PITCH + NTOK * PITCH +       // actH, actL
                                 HID * PITCH + HID * PITCH) * 2 +    // WsmH, WsmL (bf16)
                        (size_t)(NTOK + NTOK + HID) * 4;             // sArr,tArr,w2sm
    cudaFuncSetAttribute(phase_kernel<1>, cudaFuncAttributeMaxDynamicSharedMemorySize, (int)smem);
    cudaFuncSetAttribute(phase_kernel<2>, cudaFuncAttributeMaxDynamicSharedMemorySize, (int)smem);

    prep_kernel<<<768, NTHREADS>>>(W0, W1, out);
    transpose_w_kernel<<<BDIM * HDIM, NTHREADS>>>(w);
    phase_kernel<1><<<NTOT / NTOK, NTHREADS, smem>>>(x, cond, b0, b1, W2, b2, out);
    phase_kernel<2><<<NTOT / NTOK, NTHREADS, smem>>>(x, cond, b0, b1, W2, b2, out);
}

// round 3
// speedup vs baseline: 3.6192x; 1.2432x over previous
#include <cuda_runtime.h>
#include <cuda_bf16.h>
#include <math.h>
#include <stdint.h>

#define BDIM 64
#define TDIM 4096
#define CDIM 64
#define HDIM 64
#define WDIM 64
#define CONDD 16
#define HID 128
#define INDIM 81
#define K0P 96
#define NTOK 128
#define NTHREADS 256
#define PITCH 136
#define PITCH_U32 68
#define S_MAX 1.5f
#define NCHUNK_TOT 15

#define NTOT (BDIM * TDIM)
#define ZSIZE ((size_t)NTOT * 2)

__device__ float g_wT[(size_t)BDIM * HDIM * WDIM * CDIM];
__device__ __align__(16) __nv_bfloat16 g_W0h[4 * K0P * HID];
__device__ __align__(16) __nv_bfloat16 g_W0l[4 * K0P * HID];
__device__ __align__(16) __nv_bfloat16 g_W1h[12 * HID * HID];
__device__ __align__(16) __nv_bfloat16 g_W1l[12 * HID * HID];

__device__ __forceinline__ float silu_f(float z) {
    return __fdividef(z, 1.0f + __expf(-z));
}
__device__ __forceinline__ void ldsm_x4(uint32_t d[4], uint32_t saddr) {
    asm volatile("ldmatrix.sync.aligned.m8n8.x4.shared.b16 {%0,%1,%2,%3}, [%4];\n"
        : "=r"(d[0]), "=r"(d[1]), "=r"(d[2]), "=r"(d[3]) : "r"(saddr));
}
__device__ __forceinline__ void ldsm_x4_t(uint32_t d[4], uint32_t saddr) {
    asm volatile("ldmatrix.sync.aligned.m8n8.x4.trans.shared.b16 {%0,%1,%2,%3}, [%4];\n"
        : "=r"(d[0]), "=r"(d[1]), "=r"(d[2]), "=r"(d[3]) : "r"(saddr));
}
__device__ __forceinline__ void mma_bf16(float c[4], const uint32_t a[4],
                                         uint32_t b0, uint32_t b1) {
    asm volatile(
        "mma.sync.aligned.m16n8k16.row.col.f32.bf16.bf16.f32 "
        "{%0,%1,%2,%3}, {%4,%5,%6,%7}, {%8,%9}, {%0,%1,%2,%3};\n"
        : "+f"(c[0]), "+f"(c[1]), "+f"(c[2]), "+f"(c[3])
        : "r"(a[0]), "r"(a[1]), "r"(a[2]), "r"(a[3]), "r"(b0), "r"(b1));
}
__device__ __forceinline__ void cp_async16(uint32_t saddr, const void* gaddr) {
    asm volatile("cp.async.cg.shared.global [%0], [%1], 16;\n" :: "r"(saddr), "l"(gaddr));
}
template <int N>
__device__ __forceinline__ void cp_wait() {
    asm volatile("cp.async.wait_group %0;\n" :: "n"(N));
}
__device__ __forceinline__ void cp_commit() {
    asm volatile("cp.async.commit_group;\n");
}

__device__ __forceinline__ void split_store_pair(uint32_t* H, uint32_t* L,
                                                 int row, int n0, float a, float b) {
    __nv_bfloat16 ah = __float2bfloat16_rn(a);
    __nv_bfloat16 bh = __float2bfloat16_rn(b);
    float ar = a - __bfloat162float(ah);
    float br = b - __bfloat162float(bh);
    __nv_bfloat162 hp = __halves2bfloat162(ah, bh);
    __nv_bfloat162 lp = __halves2bfloat162(__float2bfloat16_rn(ar), __float2bfloat16_rn(br));
    H[row * PITCH_U32 + (n0 >> 1)] = *reinterpret_cast<uint32_t*>(&hp);
    L[row * PITCH_U32 + (n0 >> 1)] = *reinterpret_cast<uint32_t*>(&lp);
}

__device__ __forceinline__ void chunk_src(int net, int g,
                                          const __nv_bfloat16** srcH,
                                          const __nv_bfloat16** srcL) {
    if (g < 3) {
        int off = net * K0P * HID + g * 32 * HID;
        *srcH = g_W0h + off;
        *srcL = g_W0l + off;
    } else {
        int gg = g - 3;
        int gi = net * 3 + (gg >> 2);
        int off = gi * HID * HID + (gg & 3) * 32 * HID;
        *srcH = g_W1h + off;
        *srcL = g_W1l + off;
    }
}

__device__ __forceinline__ void issue_chunk(int net, int g,
                                            uint32_t WbH_s, uint32_t WbL_s, int tid) {
    const __nv_bfloat16 *srcH, *srcL;
    chunk_src(net, g, &srcH, &srcL);
#pragma unroll
    for (int q = 0; q < 2; ++q) {
        int i = tid + q * NTHREADS;
        int k = i >> 4, cc = i & 15;
        uint32_t dof = (uint32_t)((k * 17 + cc) * 16);
        cp_async16(WbH_s + dof, (const char*)srcH + (size_t)i * 16);
        cp_async16(WbL_s + dof, (const char*)srcL + (size_t)i * 16);
    }
    cp_commit();
}

__global__ void prep_kernel(const float* __restrict__ W0,
                            const float* __restrict__ W1,
                            float* __restrict__ out) {
    int idx = blockIdx.x * blockDim.x + threadIdx.x;
    if (idx < 4 * K0P * HID) {
        int i = idx / (K0P * HID);
        int r = idx % (K0P * HID);
        int k = r >> 7, nn = r & 127;
        float v = 0.0f;
        if (k <= 80) {
            int korig = (k < 80) ? (k + 1) : 0;
            v = W0[(i * HID + nn) * INDIM + korig];
        }
        __nv_bfloat16 h = __float2bfloat16_rn(v);
        g_W0h[idx] = h;
        g_W0l[idx] = __float2bfloat16_rn(v - __bfloat162float(h));
    }
    if (idx < 12 * HID * HID) {
        int g = idx >> 14;
        int r = idx & 16383;
        int k = r >> 7, nn = r & 127;
        float v = W1[(g * HID + nn) * HID + k];
        __nv_bfloat16 h = __float2bfloat16_rn(v);
        g_W1h[idx] = h;
        g_W1l[idx] = __float2bfloat16_rn(v - __bfloat162float(h));
    }
    if (idx < BDIM) out[ZSIZE + idx] = 0.0f;
}

__global__ void transpose_w_kernel(const float* __restrict__ w) {
    __shared__ float tile[64][65];
    int by = blockIdx.x;
    int b = by / HDIM, y = by % HDIM;
    int tid = threadIdx.x;
    for (int i = tid; i < 64 * 64; i += NTHREADS) {
        int c = i >> 6, xq = i & 63;
        tile[c][xq] = w[(((size_t)b * CDIM + c) * HDIM + y) * WDIM + xq];
    }
    __syncthreads();
    for (int i = tid; i < 64 * 64; i += NTHREADS) {
        int xq = i >> 6, c = i & 63;
        g_wT[(((size_t)b * HDIM + y) * WDIM + xq) * CDIM + c] = tile[c][xq];
    }
}

template <int PHASE>
__global__ __launch_bounds__(NTHREADS, 2)
void phase_kernel(const float* __restrict__ x,
                  const float* __restrict__ cond,
                  const float* __restrict__ b0g,
                  const float* __restrict__ b1g,
                  const float* __restrict__ W2g,
                  const float* __restrict__ b2g,
                  float* __restrict__ out) {
    extern __shared__ char smraw[];
    __nv_bfloat16* actH = (__nv_bfloat16*)smraw;
    __nv_bfloat16* actL = actH + NTOK * PITCH;
    __nv_bfloat16* Wb   = actL + NTOK * PITCH;          // 2 bufs x (H 32*136 + L 32*136)
    float* sArr = (float*)(Wb + 4 * 32 * PITCH);
    float* tArr = sArr + NTOK;
    float* w2sm = tArr + NTOK;

    const int tid = threadIdx.x;
    const int lane = tid & 31;
    const int wid = tid >> 5;
    const int tokBase = (wid & 1) * 64;
    const int nBase = (wid >> 1) * 32;
    const int nbase = blockIdx.x * NTOK;
    const int b = nbase >> 12;

    uint32_t actH_s = (uint32_t)__cvta_generic_to_shared(actH);
    uint32_t actL_s = (uint32_t)__cvta_generic_to_shared(actL);
    uint32_t Wb_s   = (uint32_t)__cvta_generic_to_shared(Wb);
    uint32_t* actH_u = (uint32_t*)actH;
    uint32_t* actL_u = (uint32_t*)actL;

    const int r8 = lane & 7;
    const int gA = (lane >> 3) & 1;
    const int gB = lane >> 4;

    for (int half = 0; half < 2; ++half) {
        const int net = ((PHASE == 1) ? 0 : 2) + half;

        issue_chunk(net, 0, Wb_s, Wb_s + 32 * PITCH * 2, tid);

        // ---- gather: 2 threads per token, 32 channels each ----
        {
            int tk = tid >> 1;
            int hf = tid & 1;
            int n = nbase + tk;
            float zx, zy, zkeep;
            if (PHASE == 1) { zx = x[2 * n]; zy = x[2 * n + 1]; zkeep = zy; }
            else            { zx = out[2 * n]; zy = x[2 * n + 1]; zkeep = zx; }
            float ix = zx * 63.0f, iy = zy * 63.0f;
            float ix0 = floorf(ix), iy0 = floorf(iy);
            float wx1 = ix - ix0, wx0 = 1.0f - wx1;
            float wy1 = iy - iy0, wy0 = 1.0f - wy1;
            float acc[32];
#pragma unroll
            for (int c = 0; c < 32; c++) acc[c] = 0.0f;
#pragma unroll
            for (int corner = 0; corner < 4; corner++) {
                int dx = corner & 1, dy = corner >> 1;
                float xx = ix0 + (float)dx, yy = iy0 + (float)dy;
                bool valid = (xx >= 0.0f) && (xx <= 63.0f) && (yy >= 0.0f) && (yy <= 63.0f);
                if (valid) {
                    float wgt = (dx ? wx1 : wx0) * (dy ? wy1 : wy0);
                    int xc = (int)xx, yc = (int)yy;
                    const float4* gp = (const float4*)(g_wT +
                        (((size_t)b * HDIM + yc) * WDIM + xc) * CDIM + hf * 32);
#pragma unroll
                    for (int q = 0; q < 8; q++) {
                        float4 v = gp[q];
                        acc[q * 4 + 0] += wgt * v.x;
                        acc[q * 4 + 1] += wgt * v.y;
                        acc[q * 4 + 2] += wgt * v.z;
                        acc[q * 4 + 3] += wgt * v.w;
                    }
                }
            }
#pragma unroll
            for (int c = 0; c < 16; c++)
                split_store_pair(actH_u, actL_u, tk, hf * 32 + 2 * c,
                                 acc[2 * c], acc[2 * c + 1]);
            if (hf == 0) {
#pragma unroll
                for (int j = 0; j < 8; j++) {
                    float c0 = cond[b * CONDD + 2 * j];
                    float c1 = cond[b * CONDD + 2 * j + 1];
                    split_store_pair(actH_u, actL_u, tk, 64 + 2 * j, c0, c1);
                }
            } else {
                split_store_pair(actH_u, actL_u, tk, 80, zkeep, 0.0f);
#pragma unroll
                for (int q = 41; q < 48; q++) {
                    actH_u[tk * PITCH_U32 + q] = 0u;
                    actL_u[tk * PITCH_U32 + q] = 0u;
                }
            }
        }

        int g = 0;
        for (int l = 0; l < 4; ++l) {
            const float* bias = (l == 0) ? (b0g + net * HID)
                                         : (b1g + (net * 3 + (l - 1)) * HID);
            const int nc = (l == 0) ? 3 : 4;

            float accA[2][4][4], accB[2][4][4];
#pragma unroll
            for (int mi = 0; mi < 2; mi++)
#pragma unroll
                for (int nj = 0; nj < 4; nj++)
#pragma unroll
                    for (int q = 0; q < 4; q++) { accA[mi][nj][q] = 0.0f; accB[mi][nj][q] = 0.0f; }

            for (int ch = 0; ch < nc; ++ch, ++g) {
                __syncthreads();
                if (g + 1 < NCHUNK_TOT) {
                    uint32_t base = Wb_s + (uint32_t)(((g + 1) & 1) * (32 * PITCH * 4));
                    issue_chunk(net, g + 1, base, base + 32 * PITCH * 2, tid);
                    cp_wait<1>();
                } else {
                    cp_wait<0>();
                }
                __syncthreads();

                uint32_t WH_s = Wb_s + (uint32_t)((g & 1) * (32 * PITCH * 4));
                uint32_t WL_s = WH_s + 32 * PITCH * 2;
#pragma unroll
                for (int ks = 0; ks < 2; ++ks) {
                    int colA = ch * 32 + ks * 16 + gB * 8;
                    uint32_t aH[4][4], aL[4][4];
#pragma unroll
                    for (int mi = 0; mi < 4; mi++) {
                        uint32_t off = (uint32_t)(((tokBase + mi * 16 + r8 + gA * 8) * PITCH + colA) * 2);
                        ldsm_x4(aH[mi], actH_s + off);
                        ldsm_x4(aL[mi], actL_s + off);
                    }
#pragma unroll
                    for (int nj = 0; nj < 2; nj++) {
                        uint32_t bH[4], bL[4];
                        uint32_t off = (uint32_t)(((ks * 16 + r8 + gA * 8) * PITCH +
                                                   nBase + nj * 16 + gB * 8) * 2);
                        ldsm_x4_t(bH, WH_s + off);
                        ldsm_x4_t(bL, WL_s + off);
#pragma unroll
                        for (int h2 = 0; h2 < 2; h2++) {
                            uint32_t w0 = (h2 == 0) ? bH[0] : bH[2];
                            uint32_t w1 = (h2 == 0) ? bH[1] : bH[3];
                            uint32_t v0 = (h2 == 0) ? bL[0] : bL[2];
                            uint32_t v1 = (h2 == 0) ? bL[1] : bL[3];
                            float* c0 = accA[0][nj * 2 + h2];
                            mma_bf16(c0, aH[0], w0, w1);
                            mma_bf16(c0, aH[0], v0, v1);
                            mma_bf16(c0, aL[0], w0, w1);
                            float* c1 = accA[1][nj * 2 + h2];
                            mma_bf16(c1, aH[1], w0, w1);
                            mma_bf16(c1, aH[1], v0, v1);
                            mma_bf16(c1, aL[1], w0, w1);
                            float* c2 = accB[0][nj * 2 + h2];
                            mma_bf16(c2, aH[2], w0, w1);
                            mma_bf16(c2, aH[2], v0, v1);
                            mma_bf16(c2, aL[2], w0, w1);
                            float* c3 = accB[1][nj * 2 + h2];
                            mma_bf16(c3, aH[3], w0, w1);
                            mma_bf16(c3, aH[3], v0, v1);
                            mma_bf16(c3, aL[3], w0, w1);
                        }
                    }
                }
            }
            __syncthreads();

#pragma unroll
            for (int mi = 0; mi < 2; mi++) {
                int row0 = tokBase + mi * 16 + (lane >> 2);
#pragma unroll
                for (int n8 = 0; n8 < 4; n8++) {
                    int n0 = nBase + n8 * 8 + (lane & 3) * 2;
                    float2 bb = *(const float2*)&bias[n0];
                    float* d = accA[mi][n8];
                    split_store_pair(actH_u, actL_u, row0, n0,
                                     silu_f(d[0] + bb.x), silu_f(d[1] + bb.y));
                    split_store_pair(actH_u, actL_u, row0 + 8, n0,
                                     silu_f(d[2] + bb.x), silu_f(d[3] + bb.y));
                    float* e = accB[mi][n8];
                    split_store_pair(actH_u, actL_u, row0 + 32, n0,
                                     silu_f(e[0] + bb.x), silu_f(e[1] + bb.y));
                    split_store_pair(actH_u, actL_u, row0 + 40, n0,
                                     silu_f(e[2] + bb.x), silu_f(e[3] + bb.y));
                }
            }
        }

        if (tid < HID) w2sm[tid] = W2g[net * HID + tid];
        __syncthreads();
        if (tid < NTOK) {
            float sum = 0.0f;
            int rowOff = tid * PITCH_U32;
#pragma unroll 8
            for (int i = 0; i < 64; ++i) {
                uint32_t hp = actH_u[rowOff + i];
                uint32_t lp = actL_u[rowOff + i];
                __nv_bfloat162 hv = *reinterpret_cast<__nv_bfloat162*>(&hp);
                __nv_bfloat162 lv = *reinterpret_cast<__nv_bfloat162*>(&lp);
                float v0 = __bfloat162float(hv.x) + __bfloat162float(lv.x);
                float v1 = __bfloat162float(hv.y) + __bfloat162float(lv.y);
                sum += v0 * w2sm[2 * i] + v1 * w2sm[2 * i + 1];
            }
            float* dst = (half == 0) ? sArr : tArr;
            dst[tid] = sum + b2g[net];
        }
        __syncthreads();
    }

    if (tid < NTOK) {
        int n = nbase + tid;
        float s = tanhf(sArr[tid]) * S_MAX;
        float t = tArr[tid];
        float zold = (PHASE == 1) ? x[2 * n] : x[2 * n + 1];
        out[2 * n + ((PHASE == 1) ? 0 : 1)] = zold * expf(s) + t;
        sArr[tid] = s;
    }
    __syncthreads();
    if (tid < 32) {
        float v = sArr[tid] + sArr[tid + 32] + sArr[tid + 64] + sArr[tid + 96];
#pragma unroll
        for (int off = 16; off > 0; off >>= 1) v += __shfl_down_sync(0xffffffffu, v, off);
        if (tid == 0) atomicAdd(out + ZSIZE + b, v);
    }
}

extern "C" void kernel_launch(void* const* d_in, const int* in_sizes, int n_in,
                              void* d_out, int out_size) {
    const float* x    = (const float*)d_in[0];
    const float* w    = (const float*)d_in[1];
    const float* cond = (const float*)d_in[2];
    const float* W0   = (const float*)d_in[3];
    const float* b0   = (const float*)d_in[4];
    const float* W1   = (const float*)d_in[5];
    const float* b1   = (const float*)d_in[6];
    const float* W2   = (const float*)d_in[7];
    const float* b2   = (const float*)d_in[8];
    float* out = (float*)d_out;

    const size_t smem = (size_t)(2 * NTOK * PITCH + 4 * 32 * PITCH) * 2 +
                        (size_t)(2 * NTOK + HID) * 4;
    cudaFuncSetAttribute(phase_kernel<1>, cudaFuncAttributeMaxDynamicSharedMemorySize, (int)smem);
    cudaFuncSetAttribute(phase_kernel<2>, cudaFuncAttributeMaxDynamicSharedMemorySize, (int)smem);

    prep_kernel<<<768, NTHREADS>>>(W0, W1, out);
    transpose_w_kernel<<<BDIM * HDIM, NTHREADS>>>(w);
    phase_kernel<1><<<NTOT / NTOK, NTHREADS, smem>>>(x, cond, b0, b1, W2, b2, out);
    phase_kernel<2><<<NTOT / NTOK, NTHREADS, smem>>>(x, cond, b0, b1, W2, b2, out);
}